// round 8
// baseline (speedup 1.0000x reference)
#include <cuda_runtime.h>

// FIRApply: y[t] = sum_{k=0}^{15} b[k] * x[t-k], zero initial state.
// x: [64, 480000] f32, b: [16] f32, y: [64, 480000] f32.
//
// Dense mapping, two positions per thread: lane i owns outputs
// [tA, tA+3] and [tA+1024, tA+1027], tA = 2048*bx + 4*tid.
// Each window is 5 dense LDG.128 (16B lane stride -> 4 L1 wavefronts per
// warp-instruction, the coalesced minimum); the 5x read overlap hits L1.
// Interior blocks take a fully unconditional path (no predicates, immediate
// offsets off two bases); only block 0 (zero history) and the last block
// (ragged tail) run the guarded path.

#define BATCH  64
#define T_LEN  480000
#define NTAPS  16
#define TPB    256
#define HALF   (4*TPB)        // 1024 outputs per half-tile
#define OPB    (2*HALF)       // 2048 outputs per block
#define NBLK   ((T_LEN + OPB - 1) / OPB)   // 235

__constant__ float c_b[NTAPS];

// window w[0..19] = x[t0-16 .. t0+3]; acc[o] = sum_k b[k]*w[o+16-k]
__device__ __forceinline__ void fir_win(const float* __restrict__ w,
                                        float4& out)
{
    float acc[4];
#pragma unroll
    for (int o = 0; o < 4; o++) {
        float s = 0.0f;
#pragma unroll
        for (int k = 0; k < NTAPS; k++)
            s = fmaf(c_b[k], w[o + 16 - k], s);
        acc[o] = s;
    }
    out = make_float4(acc[0], acc[1], acc[2], acc[3]);
}

__device__ __forceinline__ void load_win_fast(const float* __restrict__ xr,
                                              int t0, float* __restrict__ w)
{
#pragma unroll
    for (int c = 0; c < 5; c++) {
        float4 v = __ldg(reinterpret_cast<const float4*>(xr + t0 - 16 + 4 * c));
        w[4*c+0] = v.x; w[4*c+1] = v.y; w[4*c+2] = v.z; w[4*c+3] = v.w;
    }
}

__device__ __forceinline__ void load_win_guard(const float* __restrict__ xr,
                                               int t0, float* __restrict__ w)
{
#pragma unroll
    for (int c = 0; c < 5; c++) {
        const int g = t0 - 16 + 4 * c;       // multiple of 4: float4 all-in or all-out
        float4 v = (g >= 0 && g < T_LEN)
            ? __ldg(reinterpret_cast<const float4*>(xr + g))
            : make_float4(0.f, 0.f, 0.f, 0.f);
        w[4*c+0] = v.x; w[4*c+1] = v.y; w[4*c+2] = v.z; w[4*c+3] = v.w;
    }
}

__global__ __launch_bounds__(TPB)
void fir_kernel(const float* __restrict__ x,
                float* __restrict__ y)
{
    const int row = blockIdx.y;
    const int bx  = blockIdx.x;
    const int tA  = bx * OPB + threadIdx.x * 4;
    const int tB  = tA + HALF;

    const float* __restrict__ xr = x + (long long)row * T_LEN;
    float*       __restrict__ yr = y + (long long)row * T_LEN;

    if (bx > 0 && bx < NBLK - 1) {
        // ---- interior: fully unconditional, 10 LDG.128 off two bases ----
        float wA[20], wB[20];
        load_win_fast(xr, tA, wA);
        load_win_fast(xr, tB, wB);
        float4 oA, oB;
        fir_win(wA, oA);
        fir_win(wB, oB);
        *reinterpret_cast<float4*>(yr + tA) = oA;
        *reinterpret_cast<float4*>(yr + tB) = oB;
    } else {
        // ---- block 0 (zero history) or last block (ragged tail) ----
        if (tA < T_LEN) {
            float wA[20];
            load_win_guard(xr, tA, wA);
            float4 oA;
            fir_win(wA, oA);
            *reinterpret_cast<float4*>(yr + tA) = oA;
        }
        if (tB < T_LEN) {
            float wB[20];
            load_win_guard(xr, tB, wB);
            float4 oB;
            fir_win(wB, oB);
            *reinterpret_cast<float4*>(yr + tB) = oB;
        }
    }
}

extern "C" void kernel_launch(void* const* d_in, const int* in_sizes, int n_in,
                              void* d_out, int out_size)
{
    const float* x = (const float*)d_in[0];
    const float* b = (const float*)d_in[1];
    float* y = (float*)d_out;

    cudaMemcpyToSymbolAsync(c_b, b, NTAPS * sizeof(float), 0,
                            cudaMemcpyDeviceToDevice);

    dim3 grid(NBLK, BATCH);   // (235, 64)
    fir_kernel<<<grid, TPB>>>(x, y);
}

// round 9
// speedup vs baseline: 1.0099x; 1.0099x over previous
#include <cuda_runtime.h>

// FIRApply: y[t] = sum_{k=0}^{15} b[k] * x[t-k], zero initial state.
// x: [64, 480000] f32, b: [16] f32, y: [64, 480000] f32.
//
// Dense single-window mapping: thread owns 4 consecutive outputs at
// t0 = 2048*bx + 4*tid (TPB=512). Window x[t0-16 .. t0+3] = 5 LDG.128,
// each dense across the warp (16B lane stride -> minimal L1 wavefronts);
// redundant reads hit L1. Interior blocks are fully branch-free (no
// predicates -> no ALU tax, R7's failure mode); only block 0 (zero
// history) and the last block (ragged tail) take the guarded path.
// Low register count + TPB=512 targets 4 CTAs/SM (100% occupancy),
// MLP_p1=5 keeps cross-CTA L1tex-queue spread near the floor.

#define BATCH  64
#define T_LEN  480000
#define NTAPS  16
#define TPB    512
#define OPT    4
#define OPB    (OPT*TPB)                      // 2048 outputs per block
#define NBLK   ((T_LEN + OPB - 1) / OPB)      // 235

__constant__ float c_b[NTAPS];

__device__ __forceinline__ float4 fir_win(const float* __restrict__ w)
{
    float acc[4];
#pragma unroll
    for (int o = 0; o < 4; o++) {
        float s = 0.0f;
#pragma unroll
        for (int k = 0; k < NTAPS; k++)
            s = fmaf(c_b[k], w[o + 16 - k], s);
        acc[o] = s;
    }
    return make_float4(acc[0], acc[1], acc[2], acc[3]);
}

__global__ __launch_bounds__(TPB, 4)
void fir_kernel(const float* __restrict__ x,
                float* __restrict__ y)
{
    const int row = blockIdx.y;
    const int bx  = blockIdx.x;
    const int t0  = bx * OPB + threadIdx.x * OPT;

    const float* __restrict__ xr = x + (long long)row * T_LEN;
    float*       __restrict__ yr = y + (long long)row * T_LEN;

    float w[20];

    if (bx > 0 && bx < NBLK - 1) {
        // ---- interior: branch-free, 5 unconditional dense LDG.128 ----
#pragma unroll
        for (int c = 0; c < 5; c++) {
            float4 v = __ldg(reinterpret_cast<const float4*>(xr + t0 - 16 + 4 * c));
            w[4*c+0] = v.x; w[4*c+1] = v.y; w[4*c+2] = v.z; w[4*c+3] = v.w;
        }
        *reinterpret_cast<float4*>(yr + t0) = fir_win(w);
    } else {
        // ---- block 0 (zero history) or last block (ragged tail) ----
        if (t0 < T_LEN) {
#pragma unroll
            for (int c = 0; c < 5; c++) {
                const int g = t0 - 16 + 4 * c;   // multiple of 4: all-in or all-out
                float4 v = (g >= 0 && g < T_LEN)
                    ? __ldg(reinterpret_cast<const float4*>(xr + g))
                    : make_float4(0.f, 0.f, 0.f, 0.f);
                w[4*c+0] = v.x; w[4*c+1] = v.y; w[4*c+2] = v.z; w[4*c+3] = v.w;
            }
            *reinterpret_cast<float4*>(yr + t0) = fir_win(w);
        }
    }
}

extern "C" void kernel_launch(void* const* d_in, const int* in_sizes, int n_in,
                              void* d_out, int out_size)
{
    const float* x = (const float*)d_in[0];
    const float* b = (const float*)d_in[1];
    float* y = (float*)d_out;

    cudaMemcpyToSymbolAsync(c_b, b, NTAPS * sizeof(float), 0,
                            cudaMemcpyDeviceToDevice);

    dim3 grid(NBLK, BATCH);   // (235, 64)
    fir_kernel<<<grid, TPB>>>(x, y);
}